// round 14
// baseline (speedup 1.0000x reference)
#include <cuda_runtime.h>

// LIF_ASC: T=4096 serial steps, B=256, N=12. Cycle model (validated R4-R13):
// pointwise(12) + STS->LDS exchange(~60) + dot(20) ~ 94 cyc/step; exchange binds.
// R14 = R10 byte-for-byte EXCEPT the transport of the 12 exchanged values:
//   A[0..7]  -> 8 width-16 SHFL broadcasts (first return ~+34; feed dot levels 1-2)
//   A[8..11] -> STS + one volatile v4 LDS   (return ~+60; feeds dot level 3)
// The two transport latencies OVERLAP instead of adding. Dot expression tree
// and value bits are identical to R10 -> rel_err must be exactly 2.650908e-07.

#define TT 4096
#define BB 256
#define NN 12
#define CH 8

__device__ __forceinline__ float fmul_sat(float a, float b) {
    float r; asm("mul.rn.sat.f32 %0, %1, %2;" : "=f"(r) : "f"(a), "f"(b));
    return r;
}
__device__ __forceinline__ float ffma_sat(float a, float b, float c) {
    float r; asm("fma.rn.sat.f32 %0, %1, %2, %3;" : "=f"(r) : "f"(a), "f"(b), "f"(c));
    return r;
}

// Volatile smem half of the exchange: write this lane's a, read A[8..11].
// Internally ordered (volatile), no global-memory clobber.
__device__ __forceinline__ void exchange_tail4(unsigned waddr, unsigned raddr32,
                                               float a, float* o) {
    asm volatile(
        "st.volatile.shared.b32 [%4], %5;\n\t"
        "ld.volatile.shared.v4.f32 {%0,%1,%2,%3}, [%6];\n\t"
        : "=f"(o[0]), "=f"(o[1]), "=f"(o[2]), "=f"(o[3])
        : "r"(waddr), "f"(a), "r"(raddr32));
}

__global__ void __launch_bounds__(32, 1) lif_asc_kernel(
    const float* __restrict__ x_in,
    const float* __restrict__ w,
    const float* __restrict__ G,
    const float* __restrict__ E_L,
    const float* __restrict__ tau_m,
    const float* __restrict__ tau_s,
    const float* __restrict__ f_I,
    const int*   __restrict__ neuron_types,
    float* __restrict__ out)
{
    const int lane = threadIdx.x & 31;
    const int g    = lane >> 4;               // batch group within warp (0/1)
    const int n    = lane & 15;               // neuron slot (active if < 12)
    const int nc   = (n < NN) ? n : (NN - 1);
    const int b    = blockIdx.x * 2 + g;
    const bool active = (n < NN);

    // Per-neuron params (runtime loads, exactly as R10 -> identical numerics).
    const float gG = G[nc];
    const float el = E_L[nc];
    const float tm = tau_m[nc];
    const float ts = tau_s[nc];
    const float fi = f_I[nc];

    const float thr     = 30.0f;
    const float norm_R  = (thr - el) * 1.1f;
    const float inv_tm  = 1.0f / tm;
    const float kA      = gG * el * inv_tm;
    const float kB      = gG * inv_tm;
    const float kV      = 1.0f - kB;
    const float kC      = norm_R * inv_tm;
    const float kC175   = kC * 1.75f;
    const float invthr  = 1.0f / thr;
    const float inv_dEL = 1.0f / (thr - el);
    const float ninv_dE = -inv_dEL;
    const float its     = 1.0f / ts;
    const float om_its  = 1.0f - its;
    const float om_f    = 1.0f - fi;
    const float BIG     = 1e30f;
    const float nThrBIG = -thr * BIG;

    // Weight column (0.5, sign, diag mask, kC folded) — same as R10.
    float wck[NN];
    #pragma unroll
    for (int j = 0; j < NN; j++) {
        float wj = 0.0f;
        if (active && j != n)
            wj = kC * 0.5f * w[j * NN + n] * (float)neuron_types[j];
        wck[j] = wj;
    }

    // Exchange buffer for the smem half (A[8..11]); full 12 stored so layout
    // stays simple (each lane writes its own slot).
    __shared__ __align__(16) float buf[32];
    const unsigned sbase   = (unsigned)__cvta_generic_to_shared(buf);
    const unsigned waddr   = sbase + 4u * (g * 16 + n);
    const unsigned raddr32 = sbase + 4u * (g * 16) + 32u;   // &A[8], 16B aligned

    float v = 0.0f, s = 0.0f, Ia = 0.0f, a = 0.0f;

    const int stride = BB * NN;
    const float* xp = x_in + b * NN + nc;     // clamped: always in-bounds
    float*       op = out  + b * NN + nc;

    // Prime first chunk.
    float xb[CH];
    #pragma unroll
    for (int k = 0; k < CH; k++)
        xb[k] = xp[k * stride];

    for (int tc = 0; tc < TT; tc += CH) {
        const int nb = min(tc + CH, TT - CH);  // clamped base: tail re-reads
        const float* xpn = xp + nb * stride;
        float* opc = op + tc * stride;
        float xn[CH];

        #pragma unroll
        for (int k = 0; k < CH; k++) {
            // ---- exchange, two parallel transports ----
            // smem path first (starts the slow round trip immediately):
            float At[4];
            exchange_tail4(waddr, raddr32, a, At);
            // shuffle path for the early dot levels (independent broadcasts):
            const float s0 = __shfl_sync(0xFFFFFFFFu, a, 0, 16);
            const float s1 = __shfl_sync(0xFFFFFFFFu, a, 1, 16);
            const float s2_ = __shfl_sync(0xFFFFFFFFu, a, 2, 16);
            const float s3 = __shfl_sync(0xFFFFFFFFu, a, 3, 16);
            const float s4 = __shfl_sync(0xFFFFFFFFu, a, 4, 16);
            const float s5 = __shfl_sync(0xFFFFFFFFu, a, 5, 16);
            const float s6 = __shfl_sync(0xFFFFFFFFu, a, 6, 16);
            const float s7 = __shfl_sync(0xFFFFFFFFu, a, 7, 16);

            // ---- prefetch (off-chain) ----
            xn[k] = xpn[k * stride];

            // ---- off-chain precomputes (entering state) ----
            const float init  = fmaf(xb[k], kC175, fmaf(v, kV, kA));
            const float voffn = v * ninv_dE;
            const float spre  = s * om_its;
            const float iam   = Ia * om_f;
            const float P     = spre + iam;

            // ---- dot: EXACT R10 expression tree; only transports differ ----
            float acc0 = fmaf(s0, wck[0], init);
            float acc1 = s1  * wck[1];
            float acc2 = s2_ * wck[2];
            float acc3 = s3  * wck[3];
            acc0 = fmaf(s4, wck[4], acc0);
            acc1 = fmaf(s5, wck[5], acc1);
            acc2 = fmaf(s6, wck[6], acc2);
            acc3 = fmaf(s7, wck[7], acc3);
            acc0 = fmaf(At[0], wck[8],  acc0);
            acc1 = fmaf(At[1], wck[9],  acc1);
            acc2 = fmaf(At[2], wck[10], acc2);
            acc3 = fmaf(At[3], wck[11], acc3);
            const float v_next = (acc0 + acc1) + (acc2 + acc3);

            // ---- chain pointwise: a(t+1) at v_next+12 ----
            const float gating = fmul_sat(v_next, invthr);
            const float dvclip = ffma_sat(v_next, inv_dEL, voffn);
            const float spk01  = ffma_sat(v_next, BIG, nThrBIG);
            const float m      = gating * dvclip;
            const float Pspk   = fmaf(spk01, fi, P);
            a = fmaf(m, its, Pspk);

            // ---- off-chain state (ALU pipe) + output ----
            const bool spiked = (v_next >= thr);
            v  = spiked ? el : v_next;
            Ia = iam + (spiked ? fi : 0.0f);
            const float s2 = fmaf(m, its, spre);
            s  = s2;
            if (active) opc[k * stride] = s2 * ts;
        }

        #pragma unroll
        for (int k = 0; k < CH; k++) xb[k] = xn[k];
    }
}

extern "C" void kernel_launch(void* const* d_in, const int* in_sizes, int n_in,
                              void* d_out, int out_size) {
    const float* x_in  = (const float*)d_in[0];
    const float* w     = (const float*)d_in[1];
    const float* G     = (const float*)d_in[2];
    const float* E_L   = (const float*)d_in[3];
    const float* tau_m = (const float*)d_in[4];
    const float* tau_s = (const float*)d_in[5];
    const float* f_I   = (const float*)d_in[6];
    const int*   nt    = (const int*)d_in[7];
    float* out = (float*)d_out;

    (void)in_sizes; (void)n_in; (void)out_size;

    // 128 blocks x 1 warp: one warp per SM, 2 batches per warp.
    lif_asc_kernel<<<BB / 2, 32>>>(x_in, w, G, E_L, tau_m, tau_s, f_I, nt, out);
}

// round 15
// speedup vs baseline: 1.0984x; 1.0984x over previous
#include <cuda_runtime.h>

// LIF_ASC: T=4096 serial steps, B=256, N=12. Period ~94ns/step, bound by the
// a->STS->LDS->dot->pointwise cycle; STS/LDS/LDG/STG share ONE in-order MIO
// queue (validated: R12 regressed 50us by putting STG/LDG before the LDS;
// R7/R14 regressed via SHFL occupancy on the same queue).
// R15 = R10 byte-for-byte + ONE change: each step's STG is DEFERRED one step
// and issued right after the next step's exchange (inside the ~60-cyc LDS
// shadow) instead of at step end (directly ahead of the next critical STS).

#define TT 4096
#define BB 256
#define NN 12
#define CH 8

__device__ __forceinline__ float fmul_sat(float a, float b) {
    float r; asm("mul.rn.sat.f32 %0, %1, %2;" : "=f"(r) : "f"(a), "f"(b));
    return r;
}
__device__ __forceinline__ float ffma_sat(float a, float b, float c) {
    float r; asm("fma.rn.sat.f32 %0, %1, %2, %3;" : "=f"(r) : "f"(a), "f"(b), "f"(c));
    return r;
}

// Fused exchange: write this lane's a, read the 12 group values.
// Ordered internally (volatile shared), NO global memory clobber.
__device__ __forceinline__ void exchange12(unsigned waddr, unsigned raddr,
                                           float a, float* o) {
    asm volatile(
        "st.volatile.shared.b32 [%12], %13;\n\t"
        "ld.volatile.shared.v4.f32 {%0,%1,%2,%3}, [%14];\n\t"
        "ld.volatile.shared.v4.f32 {%4,%5,%6,%7}, [%14+16];\n\t"
        "ld.volatile.shared.v4.f32 {%8,%9,%10,%11}, [%14+32];\n\t"
        : "=f"(o[0]), "=f"(o[1]), "=f"(o[2]),  "=f"(o[3]),
          "=f"(o[4]), "=f"(o[5]), "=f"(o[6]),  "=f"(o[7]),
          "=f"(o[8]), "=f"(o[9]), "=f"(o[10]), "=f"(o[11])
        : "r"(waddr), "f"(a), "r"(raddr));
}

__global__ void __launch_bounds__(32, 1) lif_asc_kernel(
    const float* __restrict__ x_in,
    const float* __restrict__ w,
    const float* __restrict__ G,
    const float* __restrict__ E_L,
    const float* __restrict__ tau_m,
    const float* __restrict__ tau_s,
    const float* __restrict__ f_I,
    const int*   __restrict__ neuron_types,
    float* __restrict__ out)
{
    const int lane = threadIdx.x & 31;
    const int g    = lane >> 4;               // batch group within warp (0/1)
    const int n    = lane & 15;               // neuron slot (active if < 12)
    const int nc   = (n < NN) ? n : (NN - 1);
    const int b    = blockIdx.x * 2 + g;
    const bool active = (n < NN);

    // Per-neuron params (runtime loads, exactly as R10 -> identical numerics).
    const float gG = G[nc];
    const float el = E_L[nc];
    const float tm = tau_m[nc];
    const float ts = tau_s[nc];
    const float fi = f_I[nc];

    const float thr     = 30.0f;
    const float norm_R  = (thr - el) * 1.1f;
    const float inv_tm  = 1.0f / tm;
    const float kA      = gG * el * inv_tm;
    const float kB      = gG * inv_tm;
    const float kV      = 1.0f - kB;
    const float kC      = norm_R * inv_tm;
    const float kC175   = kC * 1.75f;
    const float invthr  = 1.0f / thr;
    const float inv_dEL = 1.0f / (thr - el);
    const float ninv_dE = -inv_dEL;
    const float its     = 1.0f / ts;
    const float om_its  = 1.0f - its;
    const float om_f    = 1.0f - fi;
    const float BIG     = 1e30f;
    const float nThrBIG = -thr * BIG;

    // Weight column (0.5, sign, diag mask, kC folded) — same as R10.
    float wck[NN];
    #pragma unroll
    for (int j = 0; j < NN; j++) {
        float wj = 0.0f;
        if (active && j != n)
            wj = kC * 0.5f * w[j * NN + n] * (float)neuron_types[j];
        wck[j] = wj;
    }

    // Single exchange buffer (ordered volatile shared ops).
    __shared__ __align__(16) float buf[32];
    const unsigned sbase = (unsigned)__cvta_generic_to_shared(buf);
    const unsigned waddr = sbase + 4u * (g * 16 + n);
    const unsigned raddr = sbase + 4u * (g * 16);

    float v = 0.0f, s = 0.0f, Ia = 0.0f, a = 0.0f;

    const int stride = BB * NN;
    const float* xp = x_in + b * NN + nc;     // clamped: always in-bounds
    float*       op = out  + b * NN + nc;

    // Deferred output store (value + address of the PREVIOUS step's result).
    // Primed to a harmless dummy: rewrite of out[0] happens before the real
    // out[0] store. First real pend is set by step 0 below.
    float  pend_v = 0.0f;
    float* pend_p = op;          // overwritten by step 0's real value before
    bool   pend_live = false;    // compile-time-ish: only first iteration skips

    // Prime first chunk.
    float xb[CH];
    #pragma unroll
    for (int k = 0; k < CH; k++)
        xb[k] = xp[k * stride];

    for (int tc = 0; tc < TT; tc += CH) {
        const int nb = min(tc + CH, TT - CH);  // clamped base: tail re-reads
        const float* xpn = xp + nb * stride;
        float* opc = op + tc * stride;
        float xn[CH];

        #pragma unroll
        for (int k = 0; k < CH; k++) {
            // ---- exchange a (critical): fused STS+3xLDS ----
            float A[NN];
            exchange12(waddr, raddr, a, A);

            // ---- DEFERRED STG: previous step's output, issued in the LDS
            //      shadow (behind the in-flight LDS, ~55cyc ahead of the
            //      next step's critical STS) ----
            if (pend_live && active) *pend_p = pend_v;

            // ---- prefetch (off-chain, also in the shadow) ----
            xn[k] = xpn[k * stride];

            // ---- off-chain precomputes (entering state) ----
            const float init  = fmaf(xb[k], kC175, fmaf(v, kV, kA));
            const float voffn = v * ninv_dE;
            const float spre  = s * om_its;
            const float iam   = Ia * om_f;
            const float P     = spre + iam;

            // ---- dot: EXACT R4/R10 4-accumulator order ----
            float acc0 = fmaf(A[0], wck[0], init);
            float acc1 = A[1] * wck[1];
            float acc2 = A[2] * wck[2];
            float acc3 = A[3] * wck[3];
            acc0 = fmaf(A[4],  wck[4],  acc0);
            acc1 = fmaf(A[5],  wck[5],  acc1);
            acc2 = fmaf(A[6],  wck[6],  acc2);
            acc3 = fmaf(A[7],  wck[7],  acc3);
            acc0 = fmaf(A[8],  wck[8],  acc0);
            acc1 = fmaf(A[9],  wck[9],  acc1);
            acc2 = fmaf(A[10], wck[10], acc2);
            acc3 = fmaf(A[11], wck[11], acc3);
            const float v_next = (acc0 + acc1) + (acc2 + acc3);

            // ---- chain pointwise: a(t+1) at v_next+12 ----
            const float gating = fmul_sat(v_next, invthr);
            const float dvclip = ffma_sat(v_next, inv_dEL, voffn);
            const float spk01  = ffma_sat(v_next, BIG, nThrBIG);
            const float m      = gating * dvclip;
            const float Pspk   = fmaf(spk01, fi, P);
            a = fmaf(m, its, Pspk);

            // ---- off-chain state (ALU pipe); output goes to pending ----
            const bool spiked = (v_next >= thr);
            v  = spiked ? el : v_next;
            Ia = iam + (spiked ? fi : 0.0f);
            const float s2 = fmaf(m, its, spre);
            s  = s2;
            pend_v = s2 * ts;
            pend_p = opc + k * stride;
            pend_live = true;
        }

        #pragma unroll
        for (int k = 0; k < CH; k++) xb[k] = xn[k];
    }

    // Final deferred store (last step's output).
    if (active) *pend_p = pend_v;
}

extern "C" void kernel_launch(void* const* d_in, const int* in_sizes, int n_in,
                              void* d_out, int out_size) {
    const float* x_in  = (const float*)d_in[0];
    const float* w     = (const float*)d_in[1];
    const float* G     = (const float*)d_in[2];
    const float* E_L   = (const float*)d_in[3];
    const float* tau_m = (const float*)d_in[4];
    const float* tau_s = (const float*)d_in[5];
    const float* f_I   = (const float*)d_in[6];
    const int*   nt    = (const int*)d_in[7];
    float* out = (float*)d_out;

    (void)in_sizes; (void)n_in; (void)out_size;

    // 128 blocks x 1 warp: one warp per SM, 2 batches per warp.
    lif_asc_kernel<<<BB / 2, 32>>>(x_in, w, G, E_L, tau_m, tau_s, f_I, nt, out);
}